// round 7
// baseline (speedup 1.0000x reference)
#include <cuda_runtime.h>

#define TT  1024
#define NB  128
#define VV  35
#define HH  512
#define VS  128
#define KSZ 128
#define G1  2048
#define ML  250
#define NBLK 128

typedef unsigned long long ull;

__device__ float d_inpc[NB*G1];
__device__ float d_toktab[VV*G1];
__device__ float d_h1[2][NB*HH];
__device__ float d_c1[NB*HH];
__device__ float d_h2[2][NB*KSZ];
__device__ float d_c2[NB*KSZ];
__device__ int   d_tok[NB];
__device__ unsigned d_barcnt, d_bargen;
__device__ int   d_units[1024];
__device__ int   d_U;
__device__ float d_pm[NB*8], d_ps[NB*8];
__device__ float d_pctx[NB*8*VS];

__device__ __forceinline__ void ffma2(ull& c, ull a, ull b) {
    asm("fma.rn.f32x2 %0, %1, %2, %0;" : "+l"(c) : "l"(a), "l"(b));
}
__device__ __forceinline__ float2 unpack2(ull v) {
    unsigned lo, hi;
    asm("mov.b64 {%0, %1}, %2;" : "=r"(lo), "=r"(hi) : "l"(v));
    return make_float2(__uint_as_float(lo), __uint_as_float(hi));
}
__device__ __forceinline__ float sigf(float x) { return 1.0f / (1.0f + expf(-x)); }

__device__ __forceinline__ void grid_bar() {
    __threadfence();
    __syncthreads();
    if (threadIdx.x == 0) {
        volatile unsigned* genp = &d_bargen;
        unsigned gen = *genp;
        if (atomicAdd(&d_barcnt, 1u) == NBLK - 1) {
            d_barcnt = 0; __threadfence(); *genp = gen + 1;
        } else { while (*genp == gen) { } }
        __threadfence();
    }
    __syncthreads();
}

// ---- single fused precompute: vmean->inpc, toktab, state init, unit list ----
__global__ void __launch_bounds__(256) k_pre(const float* __restrict__ val,
        const float* __restrict__ emb, const float* __restrict__ Wih1,
        const float* __restrict__ bih1, const float* __restrict__ bhh1,
        const int* __restrict__ lens) {
    __shared__ float vp[2][VS];
    __shared__ float vm[VS];
    __shared__ float e[HH];
    int n = blockIdx.x, tid = threadIdx.x;
    {
        int ch = tid & 127, hp = tid >> 7;
        const float* p = val + (size_t)hp*NB*VS + n*VS + ch;
        float s = 0.f;
        #pragma unroll 8
        for (int t = 0; t < TT/2; t++) s += p[(size_t)t*2*NB*VS];
        vp[hp][ch] = s;
    }
    __syncthreads();
    if (tid < VS) vm[tid] = (vp[0][tid] + vp[1][tid]) * (1.0f/TT);
    __syncthreads();
    for (int j = tid; j < G1; j += 256) {
        const float4* w4 = (const float4*)(Wih1 + (size_t)j*(HH+VS) + HH);
        float s = 0.f;
        #pragma unroll 8
        for (int v = 0; v < VS/4; v++) {
            float4 w = w4[v];
            s += w.x*vm[4*v] + w.y*vm[4*v+1] + w.z*vm[4*v+2] + w.w*vm[4*v+3];
        }
        d_inpc[n*G1 + j] = s + bih1[j] + bhh1[j];
    }
    if (n < VV) {
        for (int k = tid; k < HH; k += 256) e[k] = emb[n*HH + k];
        __syncthreads();
        for (int j = tid; j < G1; j += 256) {
            const float4* w4 = (const float4*)(Wih1 + (size_t)j*(HH+VS));
            float s = 0.f;
            #pragma unroll 8
            for (int k = 0; k < HH/4; k++) {
                float4 w = w4[k];
                s += w.x*e[4*k] + w.y*e[4*k+1] + w.z*e[4*k+2] + w.w*e[4*k+3];
            }
            d_toktab[n*G1 + j] = s;
        }
    }
    for (int i = tid; i < HH; i += 256) { d_h1[0][n*HH+i] = 0.f; d_c1[n*HH+i] = 0.f; }
    if (tid < KSZ) { d_h2[0][n*KSZ+tid] = 0.f; d_c2[n*KSZ+tid] = 0.f; }
    if (tid == 0) d_tok[n] = 0;
    if (n == 0 && tid == 0) {
        int u = 0;
        for (int b = 0; b < NB; b++) {
            int cn = (lens[b] + 127) >> 7;
            for (int c = 0; c < cn; c++) d_units[u++] = (b << 8) | c;
        }
        d_U = u;
    }
}

struct SMem {
    union {
        struct { float As[2][32][34]; float2 Bs[2][32][67]; float gt[2][64][33]; } l1;
        struct { float As[2][32][34]; float2 Bs[2][32][34]; float gt[2][32][33]; } l2;
        struct { float h2s[KSZ]; float ev[128]; float cpart[16][VS]; float ctxs[VS];
                 float preds[VV]; float red[16], red2[16]; float fs[8]; float inv; } at;
    } u;
};

__global__ void __launch_bounds__(512, 1) k_decode(
    const float* __restrict__ key, const float* __restrict__ val,
    const int* __restrict__ lens, const float* __restrict__ Whh1,
    const float* __restrict__ Wih2, const float* __restrict__ Whh2,
    const float* __restrict__ bih2, const float* __restrict__ bhh2,
    const float* __restrict__ Wout, const float* __restrict__ bout,
    float* __restrict__ out)
{
    extern __shared__ __align__(16) char smraw[];
    SMem* sm = (SMem*)smraw;
    const int bid = blockIdx.x, tid = threadIdx.x;
    const int t = tid & 255, g = tid >> 8;
    const int lane = tid & 31, wid = tid >> 5;

    const int l1_m0 = (bid & 31) * 16, l1_n0 = (bid >> 5) * 32;
    const int l1_tn = t & 7, l1_j0 = (t >> 3) * 2;
    const int l1_la_n = t >> 3, l1_la_k = (t & 7) * 4;
    const int l1_lb_j = t >> 2, l1_lb_k = (t & 3) * 8;
    const int l1_lb_row = (l1_lb_j >> 4) * HH + l1_m0 + (l1_lb_j & 15);

    const int l2_m0 = (bid & 15) * 8, l2_n0 = (bid >> 4) * 32;
    const int l2_tn = t & 15, l2_j0 = (t >> 4) * 2;
    const int l2_la_n = t >> 3, l2_la_k = (t & 7) * 4;
    const int l2_lb_j = t >> 3, l2_lb_k = (t & 7) * 4;
    const int l2_lb_row = (l2_lb_j >> 3) * KSZ + l2_m0 + (l2_lb_j & 7);
    const int U = d_U;

    for (int step = 0; step < ML; step++) {
        const int p = step & 1;

        // ===== LSTM1 =====
        {
            const float* h1in = d_h1[p];
            const float* aptr = h1in + (size_t)(l1_n0 + l1_la_n)*HH + g*256 + l1_la_k;
            const float* bptr = Whh1 + (size_t)l1_lb_row*HH + g*256 + l1_lb_k;
            float4 av  = __ldcg((const float4*)aptr);
            float4 bv0 = *(const float4*)bptr;
            float4 bv1 = *(const float4*)(bptr + 4);
            ull a00=0, a01=0, a10=0, a11=0;
            for (int it = 0; it < 8; it++) {
                __syncthreads();
                sm->u.l1.As[g][l1_la_k+0][l1_la_n] = av.x;
                sm->u.l1.As[g][l1_la_k+1][l1_la_n] = av.y;
                sm->u.l1.As[g][l1_la_k+2][l1_la_n] = av.z;
                sm->u.l1.As[g][l1_la_k+3][l1_la_n] = av.w;
                sm->u.l1.Bs[g][l1_lb_k+0][l1_lb_j] = make_float2(bv0.x, bv0.x);
                sm->u.l1.Bs[g][l1_lb_k+1][l1_lb_j] = make_float2(bv0.y, bv0.y);
                sm->u.l1.Bs[g][l1_lb_k+2][l1_lb_j] = make_float2(bv0.z, bv0.z);
                sm->u.l1.Bs[g][l1_lb_k+3][l1_lb_j] = make_float2(bv0.w, bv0.w);
                sm->u.l1.Bs[g][l1_lb_k+4][l1_lb_j] = make_float2(bv1.x, bv1.x);
                sm->u.l1.Bs[g][l1_lb_k+5][l1_lb_j] = make_float2(bv1.y, bv1.y);
                sm->u.l1.Bs[g][l1_lb_k+6][l1_lb_j] = make_float2(bv1.z, bv1.z);
                sm->u.l1.Bs[g][l1_lb_k+7][l1_lb_j] = make_float2(bv1.w, bv1.w);
                __syncthreads();
                if (it < 7) {
                    av  = __ldcg((const float4*)(aptr + (it+1)*32));
                    bv0 = *(const float4*)(bptr + (it+1)*32);
                    bv1 = *(const float4*)(bptr + (it+1)*32 + 4);
                }
                #pragma unroll
                for (int k = 0; k < 32; k++) {
                    ull a0 = *(const ull*)&sm->u.l1.As[g][k][4*l1_tn];
                    ull a1 = *(const ull*)&sm->u.l1.As[g][k][4*l1_tn+2];
                    ull b0 = *(const ull*)&sm->u.l1.Bs[g][k][l1_j0];
                    ull b1 = *(const ull*)&sm->u.l1.Bs[g][k][l1_j0+1];
                    ffma2(a00,a0,b0); ffma2(a01,a0,b1);
                    ffma2(a10,a1,b0); ffma2(a11,a1,b1);
                }
            }
            __syncthreads();
            { float2 v;
              v=unpack2(a00); sm->u.l1.gt[g][l1_j0  ][4*l1_tn  ]=v.x; sm->u.l1.gt[g][l1_j0  ][4*l1_tn+1]=v.y;
              v=unpack2(a10); sm->u.l1.gt[g][l1_j0  ][4*l1_tn+2]=v.x; sm->u.l1.gt[g][l1_j0  ][4*l1_tn+3]=v.y;
              v=unpack2(a01); sm->u.l1.gt[g][l1_j0+1][4*l1_tn  ]=v.x; sm->u.l1.gt[g][l1_j0+1][4*l1_tn+1]=v.y;
              v=unpack2(a11); sm->u.l1.gt[g][l1_j0+1][4*l1_tn+2]=v.x; sm->u.l1.gt[g][l1_j0+1][4*l1_tn+3]=v.y; }
            __syncthreads();
            int nl = tid >> 4, mi = tid & 15;
            int gn = l1_n0 + nl, gm = l1_m0 + mi;
            int tk = __ldcg(&d_tok[gn]);
            const float* tt = d_toktab + (size_t)tk*G1;
            const float* ic = d_inpc + (size_t)gn*G1;
            float gi = sm->u.l1.gt[0][mi   ][nl] + sm->u.l1.gt[1][mi   ][nl] + tt[gm]      + ic[gm];
            float gf = sm->u.l1.gt[0][16+mi][nl] + sm->u.l1.gt[1][16+mi][nl] + tt[HH+gm]   + ic[HH+gm];
            float gg = sm->u.l1.gt[0][32+mi][nl] + sm->u.l1.gt[1][32+mi][nl] + tt[2*HH+gm] + ic[2*HH+gm];
            float go = sm->u.l1.gt[0][48+mi][nl] + sm->u.l1.gt[1][48+mi][nl] + tt[3*HH+gm] + ic[3*HH+gm];
            float cp = d_c1[gn*HH + gm];
            float cn = sigf(gf)*cp + sigf(gi)*tanhf(gg);
            d_c1[gn*HH + gm] = cn;
            d_h1[p^1][gn*HH + gm] = sigf(go)*tanhf(cn);
        }
        grid_bar();

        // ===== LSTM2 (blocks 0..63) =====
        if (bid < 64) {
            const float* A1 = d_h1[p^1];
            const float* A2 = d_h2[p];
            ull a0acc = 0, a1acc = 0;
            auto ap = [&](int it) -> const float* {
                return (it < 8)
                    ? A1 + (size_t)(l2_n0 + l2_la_n)*HH  + g*256 + it*32     + l2_la_k
                    : A2 + (size_t)(l2_n0 + l2_la_n)*KSZ + g*64  + (it-8)*32 + l2_la_k;
            };
            auto bp = [&](int it) -> const float* {
                return (it < 8)
                    ? Wih2 + (size_t)l2_lb_row*HH  + g*256 + it*32     + l2_lb_k
                    : Whh2 + (size_t)l2_lb_row*KSZ + g*64  + (it-8)*32 + l2_lb_k;
            };
            float4 av = __ldcg((const float4*)ap(0));
            float4 bv = *(const float4*)bp(0);
            for (int it = 0; it < 10; it++) {
                __syncthreads();
                sm->u.l2.As[g][l2_la_k+0][l2_la_n] = av.x;
                sm->u.l2.As[g][l2_la_k+1][l2_la_n] = av.y;
                sm->u.l2.As[g][l2_la_k+2][l2_la_n] = av.z;
                sm->u.l2.As[g][l2_la_k+3][l2_la_n] = av.w;
                sm->u.l2.Bs[g][l2_lb_k+0][l2_lb_j] = make_float2(bv.x, bv.x);
                sm->u.l2.Bs[g][l2_lb_k+1][l2_lb_j] = make_float2(bv.y, bv.y);
                sm->u.l2.Bs[g][l2_lb_k+2][l2_lb_j] = make_float2(bv.z, bv.z);
                sm->u.l2.Bs[g][l2_lb_k+3][l2_lb_j] = make_float2(bv.w, bv.w);
                __syncthreads();
                if (it < 9) { av = __ldcg((const float4*)ap(it+1)); bv = *(const float4*)bp(it+1); }
                #pragma unroll
                for (int k = 0; k < 32; k++) {
                    ull a  = *(const ull*)&sm->u.l2.As[g][k][2*l2_tn];
                    ffma2(a0acc, a, *(const ull*)&sm->u.l2.Bs[g][k][l2_j0]);
                    ffma2(a1acc, a, *(const ull*)&sm->u.l2.Bs[g][k][l2_j0+1]);
                }
            }
            __syncthreads();
            { float2 v;
              v=unpack2(a0acc); sm->u.l2.gt[g][l2_j0  ][2*l2_tn]=v.x; sm->u.l2.gt[g][l2_j0  ][2*l2_tn+1]=v.y;
              v=unpack2(a1acc); sm->u.l2.gt[g][l2_j0+1][2*l2_tn]=v.x; sm->u.l2.gt[g][l2_j0+1][2*l2_tn+1]=v.y; }
            __syncthreads();
            if (tid < 256) {
                int nl = tid >> 3, mi = tid & 7;
                int gn = l2_n0 + nl, gm = l2_m0 + mi;
                int ri = gm, rf = KSZ+gm, rg = 2*KSZ+gm, ro = 3*KSZ+gm;
                float gi = sm->u.l2.gt[0][mi   ][nl] + sm->u.l2.gt[1][mi   ][nl] + bih2[ri] + bhh2[ri];
                float gf = sm->u.l2.gt[0][8+mi ][nl] + sm->u.l2.gt[1][8+mi ][nl] + bih2[rf] + bhh2[rf];
                float gg = sm->u.l2.gt[0][16+mi][nl] + sm->u.l2.gt[1][16+mi][nl] + bih2[rg] + bhh2[rg];
                float go = sm->u.l2.gt[0][24+mi][nl] + sm->u.l2.gt[1][24+mi][nl] + bih2[ro] + bhh2[ro];
                float cp = d_c2[gn*KSZ + gm];
                float cn = sigf(gf)*cp + sigf(gi)*tanhf(gg);
                d_c2[gn*KSZ + gm] = cn;
                d_h2[p^1][gn*KSZ + gm] = sigf(go)*tanhf(cn);
            }
        }
        grid_bar();

        // ===== attention partials over balanced units =====
        {
            const float* h2c = d_h2[p^1];
            for (int u = bid; u < U; u += NBLK) {
                int pk = d_units[u];
                int n = pk >> 8, ci = pk & 255;
                int L = lens[n], t0 = ci << 7;
                int tl = min(128, L - t0);
                __syncthreads();
                if (tid < KSZ) sm->u.at.h2s[tid] = __ldcg(&h2c[(size_t)n*KSZ + tid]);
                __syncthreads();
                const float* krow = key + (size_t)t0*(NB*KSZ) + (size_t)n*KSZ + lane*4;
                const float* vrow = val + (size_t)t0*(NB*VS)  + (size_t)n*VS  + lane*4;
                float4 hv = *(const float4*)&sm->u.at.h2s[lane*4];
                #pragma unroll
                for (int q = 0; q < 4; q++) {
                    int ta = wid + q*16, tb = ta + 64;
                    float4 ka = {0,0,0,0}, kb = {0,0,0,0};
                    if (ta < tl) ka = *(const float4*)(krow + (size_t)ta*(NB*KSZ));
                    if (tb < tl) kb = *(const float4*)(krow + (size_t)tb*(NB*KSZ));
                    float sa = ka.x*hv.x + ka.y*hv.y + ka.z*hv.z + ka.w*hv.w;
                    float sb = kb.x*hv.x + kb.y*hv.y + kb.z*hv.z + kb.w*hv.w;
                    #pragma unroll
                    for (int sh = 16; sh; sh >>= 1) {
                        sa += __shfl_xor_sync(~0u, sa, sh);
                        sb += __shfl_xor_sync(~0u, sb, sh);
                    }
                    if (lane == 0) {
                        if (ta < tl) sm->u.at.ev[ta] = sa;
                        if (tb < tl) sm->u.at.ev[tb] = sb;
                    }
                }
                __syncthreads();
                float x = (tid < tl) ? sm->u.at.ev[tid] : -3.0e38f;
                #pragma unroll
                for (int sh = 16; sh; sh >>= 1) x = fmaxf(x, __shfl_xor_sync(~0u, x, sh));
                if (lane == 0) sm->u.at.red[wid] = x;
                __syncthreads();
                float m = sm->u.at.red[0];
                #pragma unroll
                for (int w = 1; w < 16; w++) m = fmaxf(m, sm->u.at.red[w]);
                float w0 = 0.f;
                if (tid < tl) { w0 = expf(sm->u.at.ev[tid] - m); sm->u.at.ev[tid] = w0; }
                #pragma unroll
                for (int sh = 16; sh; sh >>= 1) w0 += __shfl_xor_sync(~0u, w0, sh);
                if (lane == 0) sm->u.at.red2[wid] = w0;
                __syncthreads();
                float4 a0 = {0,0,0,0}, a1 = {0,0,0,0};
                #pragma unroll
                for (int q = 0; q < 4; q++) {
                    int ta = wid + q*16, tb = ta + 64;
                    if (ta < tl) {
                        float e0 = sm->u.at.ev[ta];
                        float4 v = *(const float4*)(vrow + (size_t)ta*(NB*VS));
                        a0.x += e0*v.x; a0.y += e0*v.y; a0.z += e0*v.z; a0.w += e0*v.w;
                    }
                    if (tb < tl) {
                        float e0 = sm->u.at.ev[tb];
                        float4 v = *(const float4*)(vrow + (size_t)tb*(NB*VS));
                        a1.x += e0*v.x; a1.y += e0*v.y; a1.z += e0*v.z; a1.w += e0*v.w;
                    }
                }
                a0.x += a1.x; a0.y += a1.y; a0.z += a1.z; a0.w += a1.w;
                *(float4*)&sm->u.at.cpart[wid][lane*4] = a0;
                __syncthreads();
                if (tid < VS) {
                    float s = 0.f;
                    #pragma unroll
                    for (int w = 0; w < 16; w++) s += sm->u.at.cpart[w][tid];
                    d_pctx[((size_t)n*8 + ci)*VS + tid] = s;
                }
                if (tid == 0) {
                    float st = 0.f;
                    #pragma unroll
                    for (int w = 0; w < 16; w++) st += sm->u.at.red2[w];
                    d_pm[n*8 + ci] = m;
                    d_ps[n*8 + ci] = st;
                }
            }
        }
        grid_bar();

        // ===== combine + output proj + argmax (block = row) =====
        {
            const int n = bid;
            int cn = (lens[n] + 127) >> 7;
            if (tid < KSZ) sm->u.at.h2s[tid] = __ldcg(&d_h2[p^1][(size_t)n*KSZ + tid]);
            if (tid == 0) {
                float M = -3.0e38f;
                for (int i = 0; i < cn; i++) M = fmaxf(M, __ldcg(&d_pm[n*8 + i]));
                float S = 0.f;
                for (int i = 0; i < cn; i++) {
                    float f = expf(__ldcg(&d_pm[n*8 + i]) - M);
                    sm->u.at.fs[i] = f;
                    S += f * __ldcg(&d_ps[n*8 + i]);
                }
                sm->u.at.inv = 1.0f / S;
            }
            __syncthreads();
            if (tid < VS) {
                float s = 0.f;
                for (int i = 0; i < cn; i++)
                    s += sm->u.at.fs[i] * __ldcg(&d_pctx[((size_t)n*8 + i)*VS + tid]);
                sm->u.at.ctxs[tid] = s * sm->u.at.inv;
            }
            __syncthreads();
            for (int v = wid; v < VV; v += 16) {
                const float* wr = Wout + (size_t)v*(KSZ+VS);
                float s = 0.f;
                #pragma unroll
                for (int kk = 0; kk < 8; kk++) {
                    int k = lane + kk*32;
                    float xx = (k < KSZ) ? sm->u.at.h2s[k] : sm->u.at.ctxs[k - KSZ];
                    s += xx * wr[k];
                }
                #pragma unroll
                for (int sh = 16; sh; sh >>= 1) s += __shfl_xor_sync(~0u, s, sh);
                if (lane == 0) sm->u.at.preds[v] = s + bout[v];
            }
            __syncthreads();
            if (tid < VV) out[(size_t)n*ML*VV + (size_t)step*VV + tid] = sm->u.at.preds[tid];
            if (tid == 0) {
                float best = sm->u.at.preds[0]; int bi = 0;
                #pragma unroll
                for (int v = 1; v < VV; v++)
                    if (sm->u.at.preds[v] > best) { best = sm->u.at.preds[v]; bi = v; }
                d_tok[n] = bi;
            }
        }
        grid_bar();
    }
}

extern "C" void kernel_launch(void* const* d_in, const int* in_sizes, int n_in,
                              void* d_out, int out_size) {
    const float* key  = (const float*)d_in[0];
    const float* val  = (const float*)d_in[1];
    const int*   lens = (const int*)  d_in[2];
    const float* emb  = (const float*)d_in[3];
    const float* Wih1 = (const float*)d_in[4];
    const float* bih1 = (const float*)d_in[6];
    const float* bhh1 = (const float*)d_in[7];
    const float* Whh1 = (const float*)d_in[5];
    const float* Wih2 = (const float*)d_in[8];
    const float* Whh2 = (const float*)d_in[9];
    const float* bih2 = (const float*)d_in[10];
    const float* bhh2 = (const float*)d_in[11];
    const float* Wout = (const float*)d_in[12];
    const float* bout = (const float*)d_in[13];
    float* out = (float*)d_out;

    cudaFuncSetAttribute(k_decode, cudaFuncAttributeMaxDynamicSharedMemorySize,
                         (int)sizeof(SMem));
    k_pre<<<NB, 256>>>(val, emb, Wih1, bih1, bhh1, lens);
    k_decode<<<NBLK, 512, sizeof(SMem)>>>(key, val, lens, Whh1, Wih2, Whh2,
                                          bih2, bhh2, Wout, bout, out);
}

// round 8
// speedup vs baseline: 1.1781x; 1.1781x over previous
#include <cuda_runtime.h>

#define TT  1024
#define NB  128
#define VV  35
#define HH  512
#define VS  128
#define KSZ 128
#define G1  2048
#define ML  250
#define NBLK 128

typedef unsigned long long ull;

__device__ float d_inpc[NB*G1];
__device__ float d_toktab[VV*G1];
__device__ float d_h1[2][NB*HH];
__device__ float d_c1[NB*HH];
__device__ float d_h2[2][NB*KSZ];
__device__ float d_c2[NB*KSZ];
__device__ int   d_tok[NB];
__device__ unsigned d_barcnt, d_bargen;
__device__ float4 d_Whh1d[32*512*32];   // [mtile][k][c2] (w0,w0,w1,w1)
__device__ float4 d_W2d[32*640*8];      // [mtile][k][c2]

__device__ __forceinline__ void ffma2(ull& c, ull a, ull b) {
    asm("fma.rn.f32x2 %0, %1, %2, %0;" : "+l"(c) : "l"(a), "l"(b));
}
__device__ __forceinline__ float2 unpack2(ull v) {
    unsigned lo, hi;
    asm("mov.b64 {%0, %1}, %2;" : "=r"(lo), "=r"(hi) : "l"(v));
    return make_float2(__uint_as_float(lo), __uint_as_float(hi));
}
__device__ __forceinline__ float sigf(float x) { return 1.0f / (1.0f + expf(-x)); }

__device__ __forceinline__ void grid_bar() {
    __threadfence();
    __syncthreads();
    if (threadIdx.x == 0) {
        volatile unsigned* genp = &d_bargen;
        unsigned gen = *genp;
        if (atomicAdd(&d_barcnt, 1u) == NBLK - 1) {
            d_barcnt = 0; __threadfence(); *genp = gen + 1;
        } else { while (*genp == gen) { } }
        __threadfence();
    }
    __syncthreads();
}

__global__ void __launch_bounds__(256) k_pre(const float* __restrict__ val,
        const float* __restrict__ emb, const float* __restrict__ Wih1,
        const float* __restrict__ bih1, const float* __restrict__ bhh1,
        const float* __restrict__ Whh1, const float* __restrict__ Wih2,
        const float* __restrict__ Whh2) {
    __shared__ float vp[2][VS];
    __shared__ float vm[VS];
    __shared__ float e[HH];
    int n = blockIdx.x, tid = threadIdx.x;
    {
        int ch = tid & 127, hp = tid >> 7;
        const float* p = val + (size_t)hp*NB*VS + n*VS + ch;
        float s = 0.f;
        #pragma unroll 8
        for (int t = 0; t < TT/2; t++) s += p[(size_t)t*2*NB*VS];
        vp[hp][ch] = s;
    }
    __syncthreads();
    if (tid < VS) vm[tid] = (vp[0][tid] + vp[1][tid]) * (1.0f/TT);
    __syncthreads();
    for (int j = tid; j < G1; j += 256) {
        const float4* w4 = (const float4*)(Wih1 + (size_t)j*(HH+VS) + HH);
        float s = 0.f;
        #pragma unroll 8
        for (int v = 0; v < VS/4; v++) {
            float4 w = w4[v];
            s += w.x*vm[4*v] + w.y*vm[4*v+1] + w.z*vm[4*v+2] + w.w*vm[4*v+3];
        }
        d_inpc[n*G1 + j] = s + bih1[j] + bhh1[j];
    }
    if (n < VV) {
        for (int k = tid; k < HH; k += 256) e[k] = emb[n*HH + k];
        __syncthreads();
        for (int j = tid; j < G1; j += 256) {
            const float4* w4 = (const float4*)(Wih1 + (size_t)j*(HH+VS));
            float s = 0.f;
            #pragma unroll 8
            for (int k = 0; k < HH/4; k++) {
                float4 w = w4[k];
                s += w.x*e[4*k] + w.y*e[4*k+1] + w.z*e[4*k+2] + w.w*e[4*k+3];
            }
            d_toktab[n*G1 + j] = s;
        }
    }
    // duplicated-weight tables
    int mt = n & 31, kq = n >> 5;
    for (int idx = tid; idx < 128*32; idx += 256) {
        int kk = kq*128 + (idx >> 5), c2 = idx & 31;
        int j0 = 2*c2, j1 = j0 + 1;
        int r0 = (j0 >> 4)*HH + mt*16 + (j0 & 15);
        int r1 = (j1 >> 4)*HH + mt*16 + (j1 & 15);
        float w0 = Whh1[(size_t)r0*HH + kk], w1 = Whh1[(size_t)r1*HH + kk];
        d_Whh1d[((size_t)mt*512 + kk)*32 + c2] = make_float4(w0, w0, w1, w1);
    }
    for (int idx = tid; idx < 160*8; idx += 256) {
        int kk = kq*160 + (idx >> 3), c2 = idx & 7;
        int j0 = 2*c2, j1 = j0 + 1;
        int r0 = (j0 >> 2)*KSZ + mt*4 + (j0 & 3);
        int r1 = (j1 >> 2)*KSZ + mt*4 + (j1 & 3);
        float w0 = (kk < 512) ? Wih2[(size_t)r0*HH + kk] : Whh2[(size_t)r0*KSZ + kk - 512];
        float w1 = (kk < 512) ? Wih2[(size_t)r1*HH + kk] : Whh2[(size_t)r1*KSZ + kk - 512];
        d_W2d[((size_t)mt*640 + kk)*8 + c2] = make_float4(w0, w0, w1, w1);
    }
    for (int i = tid; i < HH; i += 256) { d_h1[0][n*HH+i] = 0.f; d_c1[n*HH+i] = 0.f; }
    if (tid < KSZ) { d_h2[0][n*KSZ+tid] = 0.f; d_c2[n*KSZ+tid] = 0.f; }
    if (tid == 0) d_tok[n] = 0;
}

struct SMem {
    union {
        struct { float As[512][36]; float gt[2][64][33]; } l1;
        struct { float As[640][36]; float gt[8][16][33]; float rs[16][33]; } l2;
        struct { float h2s[KSZ]; float ev[TT]; float cpart[16][VS]; float ctxs[VS];
                 float preds[VV]; float red[16], red2[16]; } at;
    } u;
};

__global__ void __launch_bounds__(512, 1) k_decode(
    const float* __restrict__ key, const float* __restrict__ val,
    const int* __restrict__ lens,
    const float* __restrict__ bih2, const float* __restrict__ bhh2,
    const float* __restrict__ Wout, const float* __restrict__ bout,
    float* __restrict__ out)
{
    extern __shared__ __align__(16) char smraw[];
    SMem* sm = (SMem*)smraw;
    const int bid = blockIdx.x, tid = threadIdx.x;
    const int lane = tid & 31, wid = tid >> 5;
    const int mt = bid & 31, n0 = (bid >> 5) * 32;

    for (int step = 0; step < ML; step++) {
        const int p = step & 1;

        // ===== LSTM1: 32n x 64c tile, A staged once, B via LDG from dup table =====
        {
            const float* h1in = d_h1[p];
            {
                int an = tid & 31, kb = tid >> 5;
                const float* src = h1in + (size_t)(n0 + an)*HH + kb*32;
                #pragma unroll
                for (int q = 0; q < 8; q++) {
                    float4 v = __ldcg((const float4*)(src + q*4));
                    int kk = kb*32 + q*4;
                    sm->u.l1.As[kk][an] = v.x; sm->u.l1.As[kk+1][an] = v.y;
                    sm->u.l1.As[kk+2][an] = v.z; sm->u.l1.As[kk+3][an] = v.w;
                }
            }
            __syncthreads();
            const int g = tid >> 8, t = tid & 255;
            const int np = t & 7, c2 = t >> 3;
            const ulonglong2* bp = (const ulonglong2*)d_Whh1d
                                 + ((size_t)mt*512 + g*256)*32 + c2;
            ull A00=0, A01=0, A10=0, A11=0;
            #pragma unroll 8
            for (int k = 0; k < 256; k++) {
                const float* ar = &sm->u.l1.As[g*256 + k][np*4];
                ull a0 = *(const ull*)ar, a1 = *(const ull*)(ar + 2);
                ulonglong2 b = bp[(size_t)k*32];
                ffma2(A00, a0, b.x); ffma2(A10, a1, b.x);
                ffma2(A01, a0, b.y); ffma2(A11, a1, b.y);
            }
            { float2 v;
              v = unpack2(A00); sm->u.l1.gt[g][2*c2  ][np*4  ] = v.x; sm->u.l1.gt[g][2*c2  ][np*4+1] = v.y;
              v = unpack2(A10); sm->u.l1.gt[g][2*c2  ][np*4+2] = v.x; sm->u.l1.gt[g][2*c2  ][np*4+3] = v.y;
              v = unpack2(A01); sm->u.l1.gt[g][2*c2+1][np*4  ] = v.x; sm->u.l1.gt[g][2*c2+1][np*4+1] = v.y;
              v = unpack2(A11); sm->u.l1.gt[g][2*c2+1][np*4+2] = v.x; sm->u.l1.gt[g][2*c2+1][np*4+3] = v.y; }
            __syncthreads();
            int nl = tid >> 4, mi = tid & 15;
            int gn = n0 + nl, gm = mt*16 + mi;
            int tk = __ldcg(&d_tok[gn]);
            const float* tt = d_toktab + (size_t)tk*G1;
            const float* ic = d_inpc + (size_t)gn*G1;
            float gi = sm->u.l1.gt[0][mi   ][nl] + sm->u.l1.gt[1][mi   ][nl] + tt[gm]      + ic[gm];
            float gf = sm->u.l1.gt[0][16+mi][nl] + sm->u.l1.gt[1][16+mi][nl] + tt[HH+gm]   + ic[HH+gm];
            float gg = sm->u.l1.gt[0][32+mi][nl] + sm->u.l1.gt[1][32+mi][nl] + tt[2*HH+gm] + ic[2*HH+gm];
            float go = sm->u.l1.gt[0][48+mi][nl] + sm->u.l1.gt[1][48+mi][nl] + tt[3*HH+gm] + ic[3*HH+gm];
            float cp = d_c1[gn*HH + gm];
            float cn = sigf(gf)*cp + sigf(gi)*tanhf(gg);
            d_c1[gn*HH + gm] = cn;
            d_h1[p^1][gn*HH + gm] = sigf(go)*tanhf(cn);
        }
        grid_bar();

        // ===== LSTM2: 32n x 16c tile over virtual K=640, k-split 8 =====
        {
            const float* h1n = d_h1[p^1];
            const float* h2p = d_h2[p];
            {
                int an = tid & 31, kb = tid >> 5;
                #pragma unroll
                for (int q = 0; q < 10; q++) {
                    int kk = kb*40 + q*4;
                    float4 v = (kk < 512)
                        ? __ldcg((const float4*)(h1n + (size_t)(n0 + an)*HH  + kk))
                        : __ldcg((const float4*)(h2p + (size_t)(n0 + an)*KSZ + kk - 512));
                    sm->u.l2.As[kk][an] = v.x; sm->u.l2.As[kk+1][an] = v.y;
                    sm->u.l2.As[kk+2][an] = v.z; sm->u.l2.As[kk+3][an] = v.w;
                }
            }
            __syncthreads();
            const int g2 = tid >> 6, t2 = tid & 63;
            const int np = t2 & 7, c2 = t2 >> 3;
            const int kb2 = g2 * 80;
            const ulonglong2* bp = (const ulonglong2*)d_W2d
                                 + ((size_t)mt*640 + kb2)*8 + c2;
            ull A00=0, A01=0, A10=0, A11=0;
            #pragma unroll 8
            for (int k = 0; k < 80; k++) {
                const float* ar = &sm->u.l2.As[kb2 + k][np*4];
                ull a0 = *(const ull*)ar, a1 = *(const ull*)(ar + 2);
                ulonglong2 b = bp[(size_t)k*8];
                ffma2(A00, a0, b.x); ffma2(A10, a1, b.x);
                ffma2(A01, a0, b.y); ffma2(A11, a1, b.y);
            }
            { float2 v;
              v = unpack2(A00); sm->u.l2.gt[g2][2*c2  ][np*4  ] = v.x; sm->u.l2.gt[g2][2*c2  ][np*4+1] = v.y;
              v = unpack2(A10); sm->u.l2.gt[g2][2*c2  ][np*4+2] = v.x; sm->u.l2.gt[g2][2*c2  ][np*4+3] = v.y;
              v = unpack2(A01); sm->u.l2.gt[g2][2*c2+1][np*4  ] = v.x; sm->u.l2.gt[g2][2*c2+1][np*4+1] = v.y;
              v = unpack2(A11); sm->u.l2.gt[g2][2*c2+1][np*4+2] = v.x; sm->u.l2.gt[g2][2*c2+1][np*4+3] = v.y; }
            __syncthreads();
            {
                int cc = tid & 15, nl = tid >> 4;
                float s = 0.f;
                #pragma unroll
                for (int w = 0; w < 8; w++) s += sm->u.l2.gt[w][cc][nl];
                sm->u.l2.rs[cc][nl] = s;
            }
            __syncthreads();
            if (tid < 128) {
                int nl = tid >> 2, ci = tid & 3;
                int gn = n0 + nl, gm = mt*4 + ci;
                float g4[4];
                #pragma unroll
                for (int gg = 0; gg < 4; gg++) {
                    int r = gg*KSZ + gm;
                    g4[gg] = sm->u.l2.rs[gg*4 + ci][nl] + bih2[r] + bhh2[r];
                }
                float cp = d_c2[gn*KSZ + gm];
                float cn = sigf(g4[1])*cp + sigf(g4[0])*tanhf(g4[2]);
                d_c2[gn*KSZ + gm] = cn;
                d_h2[p^1][gn*KSZ + gm] = sigf(g4[3])*tanhf(cn);
            }
        }
        grid_bar();

        // ===== attention + output proj + argmax (block = batch row) =====
        {
            const int n = bid;
            float* ev = sm->u.at.ev;
            if (tid < KSZ) sm->u.at.h2s[tid] = __ldcg(&d_h2[p^1][(size_t)n*KSZ + tid]);
            __syncthreads();
            const int L = lens[n];
            const float* krow = key + (size_t)n*KSZ + (size_t)lane*4;
            const float* vrow = val + (size_t)n*VS  + (size_t)lane*4;
            float4 hv = *(const float4*)&sm->u.at.h2s[lane*4];
            float wmax = -3.0e38f;
            int t = wid;
            for (; t + 48 < L; t += 64) {
                float4 k0 = *(const float4*)(krow + (size_t)(t     )*(NB*KSZ));
                float4 k1 = *(const float4*)(krow + (size_t)(t + 16)*(NB*KSZ));
                float4 k2 = *(const float4*)(krow + (size_t)(t + 32)*(NB*KSZ));
                float4 k3 = *(const float4*)(krow + (size_t)(t + 48)*(NB*KSZ));
                float s0 = k0.x*hv.x + k0.y*hv.y + k0.z*hv.z + k0.w*hv.w;
                float s1 = k1.x*hv.x + k1.y*hv.y + k1.z*hv.z + k1.w*hv.w;
                float s2 = k2.x*hv.x + k2.y*hv.y + k2.z*hv.z + k2.w*hv.w;
                float s3 = k3.x*hv.x + k3.y*hv.y + k3.z*hv.z + k3.w*hv.w;
                #pragma unroll
                for (int sh = 16; sh; sh >>= 1) {
                    s0 += __shfl_xor_sync(~0u, s0, sh);
                    s1 += __shfl_xor_sync(~0u, s1, sh);
                    s2 += __shfl_xor_sync(~0u, s2, sh);
                    s3 += __shfl_xor_sync(~0u, s3, sh);
                }
                if (lane == 0) { ev[t]=s0; ev[t+16]=s1; ev[t+32]=s2; ev[t+48]=s3; }
                wmax = fmaxf(wmax, fmaxf(fmaxf(s0,s1), fmaxf(s2,s3)));
            }
            for (; t < L; t += 16) {
                float4 k0 = *(const float4*)(krow + (size_t)t*(NB*KSZ));
                float s0 = k0.x*hv.x + k0.y*hv.y + k0.z*hv.z + k0.w*hv.w;
                #pragma unroll
                for (int sh = 16; sh; sh >>= 1) s0 += __shfl_xor_sync(~0u, s0, sh);
                if (lane == 0) ev[t] = s0;
                wmax = fmaxf(wmax, s0);
            }
            if (lane == 0) sm->u.at.red[wid] = wmax;
            __syncthreads();
            float m = sm->u.at.red[0];
            #pragma unroll
            for (int w = 1; w < 16; w++) m = fmaxf(m, sm->u.at.red[w]);
            float psum = 0.f;
            for (int q = tid; q < L; q += 512) { float w = expf(ev[q] - m); ev[q] = w; psum += w; }
            #pragma unroll
            for (int sh = 16; sh; sh >>= 1) psum += __shfl_xor_sync(~0u, psum, sh);
            if (lane == 0) sm->u.at.red2[wid] = psum;
            __syncthreads();
            float tot = 0.f;
            #pragma unroll
            for (int w = 0; w < 16; w++) tot += sm->u.at.red2[w];
            const float inv = 1.0f / tot;
            float4 a0 = {0,0,0,0}, a1 = {0,0,0,0}, a2 = {0,0,0,0}, a3 = {0,0,0,0};
            t = wid;
            for (; t + 48 < L; t += 64) {
                float e0 = ev[t], e1 = ev[t+16], e2 = ev[t+32], e3 = ev[t+48];
                float4 v0 = *(const float4*)(vrow + (size_t)(t     )*(NB*VS));
                float4 v1 = *(const float4*)(vrow + (size_t)(t + 16)*(NB*VS));
                float4 v2 = *(const float4*)(vrow + (size_t)(t + 32)*(NB*VS));
                float4 v3 = *(const float4*)(vrow + (size_t)(t + 48)*(NB*VS));
                a0.x += e0*v0.x; a0.y += e0*v0.y; a0.z += e0*v0.z; a0.w += e0*v0.w;
                a1.x += e1*v1.x; a1.y += e1*v1.y; a1.z += e1*v1.z; a1.w += e1*v1.w;
                a2.x += e2*v2.x; a2.y += e2*v2.y; a2.z += e2*v2.z; a2.w += e2*v2.w;
                a3.x += e3*v3.x; a3.y += e3*v3.y; a3.z += e3*v3.z; a3.w += e3*v3.w;
            }
            for (; t < L; t += 16) {
                float e0 = ev[t];
                float4 v0 = *(const float4*)(vrow + (size_t)t*(NB*VS));
                a0.x += e0*v0.x; a0.y += e0*v0.y; a0.z += e0*v0.z; a0.w += e0*v0.w;
            }
            a0.x += a1.x + a2.x + a3.x; a0.y += a1.y + a2.y + a3.y;
            a0.z += a1.z + a2.z + a3.z; a0.w += a1.w + a2.w + a3.w;
            *(float4*)&sm->u.at.cpart[wid][lane*4] = a0;
            __syncthreads();
            if (tid < VS) {
                float s = 0.f;
                #pragma unroll
                for (int w = 0; w < 16; w++) s += sm->u.at.cpart[w][tid];
                sm->u.at.ctxs[tid] = s * inv;
            }
            __syncthreads();
            for (int v = wid; v < VV; v += 16) {
                const float* wr = Wout + (size_t)v*(KSZ+VS);
                float s = 0.f;
                #pragma unroll
                for (int kk = 0; kk < 8; kk++) {
                    int k = lane + kk*32;
                    float x = (k < KSZ) ? sm->u.at.h2s[k] : sm->u.at.ctxs[k-KSZ];
                    s += x * wr[k];
                }
                #pragma unroll
                for (int sh = 16; sh; sh >>= 1) s += __shfl_xor_sync(~0u, s, sh);
                if (lane == 0) sm->u.at.preds[v] = s + bout[v];
            }
            __syncthreads();
            if (tid < VV) out[(size_t)n*ML*VV + (size_t)step*VV + tid] = sm->u.at.preds[tid];
            if (tid == 0) {
                float best = sm->u.at.preds[0]; int bi = 0;
                #pragma unroll
                for (int v = 1; v < VV; v++)
                    if (sm->u.at.preds[v] > best) { best = sm->u.at.preds[v]; bi = v; }
                d_tok[n] = bi;
            }
        }
        grid_bar();
    }
}

extern "C" void kernel_launch(void* const* d_in, const int* in_sizes, int n_in,
                              void* d_out, int out_size) {
    const float* key  = (const float*)d_in[0];
    const float* val  = (const float*)d_in[1];
    const int*   lens = (const int*)  d_in[2];
    const float* emb  = (const float*)d_in[3];
    const float* Wih1 = (const float*)d_in[4];
    const float* Whh1 = (const float*)d_in[5];
    const float* bih1 = (const float*)d_in[6];
    const float* bhh1 = (const float*)d_in[7];
    const float* Wih2 = (const float*)d_in[8];
    const float* Whh2 = (const float*)d_in[9];
    const float* bih2 = (const float*)d_in[10];
    const float* bhh2 = (const float*)d_in[11];
    const float* Wout = (const float*)d_in[12];
    const float* bout = (const float*)d_in[13];
    float* out = (float*)d_out;

    cudaFuncSetAttribute(k_decode, cudaFuncAttributeMaxDynamicSharedMemorySize,
                         (int)sizeof(SMem));
    k_pre<<<NB, 256>>>(val, emb, Wih1, bih1, bhh1, Whh1, Wih2, Whh2);
    k_decode<<<NBLK, 512, sizeof(SMem)>>>(key, val, lens, bih2, bhh2, Wout, bout, out);
}

// round 9
// speedup vs baseline: 1.3583x; 1.1530x over previous
#include <cuda_runtime.h>

#define TT  1024
#define NB  128
#define VV  35
#define HH  512
#define VS  128
#define KSZ 128
#define G1  2048
#define ML  250
#define NBLK 128

typedef unsigned long long ull;

__device__ float d_inpc[NB*G1];
__device__ float d_toktab[VV*G1];
__device__ float d_h1[2][NB*HH];
__device__ float d_c1[NB*HH];
__device__ float d_h2[2][NB*KSZ];
__device__ float d_c2[NB*KSZ];
__device__ int   d_tok[NB];
__device__ unsigned d_barcnt, d_bargen;
__device__ float  d_W1t[32*512*64];     // [mt][k][c] plain transposed
__device__ float4 d_W2d[32*640*8];      // [mt][k][c2] (w0,w0,w1,w1)
__device__ int    d_srt[NB];
__device__ int    d_half[NB];
__device__ float  d_pm[NB*2], d_ps[NB*2];
__device__ float  d_pctx[NB*2*VS];

__device__ __forceinline__ ull pack2(float x) {
    unsigned r = __float_as_uint(x); ull d;
    asm("mov.b64 %0, {%1, %2};" : "=l"(d) : "r"(r), "r"(r));
    return d;
}
__device__ __forceinline__ void ffma2(ull& c, ull a, ull b) {
    asm("fma.rn.f32x2 %0, %1, %2, %0;" : "+l"(c) : "l"(a), "l"(b));
}
__device__ __forceinline__ float2 unpack2(ull v) {
    unsigned lo, hi;
    asm("mov.b64 {%0, %1}, %2;" : "=r"(lo), "=r"(hi) : "l"(v));
    return make_float2(__uint_as_float(lo), __uint_as_float(hi));
}
__device__ __forceinline__ float sigf(float x) { return 1.0f / (1.0f + expf(-x)); }

__device__ __forceinline__ void grid_bar() {
    __threadfence();
    __syncthreads();
    if (threadIdx.x == 0) {
        volatile unsigned* genp = &d_bargen;
        unsigned gen = *genp;
        if (atomicAdd(&d_barcnt, 1u) == NBLK - 1) {
            d_barcnt = 0; __threadfence(); *genp = gen + 1;
        } else { while (*genp == gen) { } }
        __threadfence();
    }
    __syncthreads();
}

__global__ void __launch_bounds__(256) k_pre(const float* __restrict__ val,
        const float* __restrict__ emb, const float* __restrict__ Wih1,
        const float* __restrict__ bih1, const float* __restrict__ bhh1,
        const float* __restrict__ Whh1, const float* __restrict__ Wih2,
        const float* __restrict__ Whh2, const int* __restrict__ lens) {
    __shared__ float vp[2][VS];
    __shared__ float vm[VS];
    __shared__ float e[HH];
    int n = blockIdx.x, tid = threadIdx.x;
    {
        int ch = tid & 127, hp = tid >> 7;
        const float* p = val + (size_t)hp*NB*VS + n*VS + ch;
        float s = 0.f;
        #pragma unroll 8
        for (int t = 0; t < TT/2; t++) s += p[(size_t)t*2*NB*VS];
        vp[hp][ch] = s;
    }
    __syncthreads();
    if (tid < VS) vm[tid] = (vp[0][tid] + vp[1][tid]) * (1.0f/TT);
    __syncthreads();
    for (int j = tid; j < G1; j += 256) {
        const float4* w4 = (const float4*)(Wih1 + (size_t)j*(HH+VS) + HH);
        float s = 0.f;
        #pragma unroll 8
        for (int v = 0; v < VS/4; v++) {
            float4 w = w4[v];
            s += w.x*vm[4*v] + w.y*vm[4*v+1] + w.z*vm[4*v+2] + w.w*vm[4*v+3];
        }
        d_inpc[n*G1 + j] = s + bih1[j] + bhh1[j];
    }
    if (n < VV) {
        for (int k = tid; k < HH; k += 256) e[k] = emb[n*HH + k];
        __syncthreads();
        for (int j = tid; j < G1; j += 256) {
            const float4* w4 = (const float4*)(Wih1 + (size_t)j*(HH+VS));
            float s = 0.f;
            #pragma unroll 8
            for (int k = 0; k < HH/4; k++) {
                float4 w = w4[k];
                s += w.x*e[4*k] + w.y*e[4*k+1] + w.z*e[4*k+2] + w.w*e[4*k+3];
            }
            d_toktab[n*G1 + j] = s;
        }
    }
    int mt = n & 31, kq = n >> 5;
    for (int idx = tid; idx < 128*64; idx += 256) {
        int kk = kq*128 + (idx >> 6), c = idx & 63;
        int r = (c >> 4)*HH + mt*16 + (c & 15);
        d_W1t[((size_t)mt*512 + kk)*64 + c] = Whh1[(size_t)r*HH + kk];
    }
    for (int idx = tid; idx < 160*8; idx += 256) {
        int kk = kq*160 + (idx >> 3), c2 = idx & 7;
        int j0 = 2*c2, j1 = j0 + 1;
        int r0 = (j0 >> 2)*KSZ + mt*4 + (j0 & 3);
        int r1 = (j1 >> 2)*KSZ + mt*4 + (j1 & 3);
        float w0 = (kk < 512) ? Wih2[(size_t)r0*HH + kk] : Whh2[(size_t)r0*KSZ + kk - 512];
        float w1 = (kk < 512) ? Wih2[(size_t)r1*HH + kk] : Whh2[(size_t)r1*KSZ + kk - 512];
        d_W2d[((size_t)mt*640 + kk)*8 + c2] = make_float4(w0, w0, w1, w1);
    }
    for (int i = tid; i < HH; i += 256) { d_h1[0][n*HH+i] = 0.f; d_c1[n*HH+i] = 0.f; }
    if (tid < KSZ) { d_h2[0][n*KSZ+tid] = 0.f; d_c2[n*KSZ+tid] = 0.f; }
    if (tid == 0) {
        d_tok[n] = 0;
        int L = lens[n];
        int h = (((L + 1) >> 1) + 15) & ~15;
        d_half[n] = (h > L) ? L : h;
    }
    if (n == 0 && tid == 0) {
        int ord[NB];
        for (int i = 0; i < NB; i++) ord[i] = i;
        for (int i = 0; i < NB-1; i++) {          // selection sort desc by lens
            int bi = i;
            for (int j = i+1; j < NB; j++)
                if (lens[ord[j]] > lens[ord[bi]]) bi = j;
            int tmp = ord[i]; ord[i] = ord[bi]; ord[bi] = tmp;
        }
        for (int i = 0; i < NB; i++) d_srt[i] = ord[i];
    }
}

struct SMem {
    union {
        struct { float As[512][36]; float gt[4][64][33]; } l1;
        struct { float As[640][36]; float gt[8][16][33]; float rs[16][33]; } l2;
        struct { float h2s[KSZ]; float ev[528]; float cpart[16][VS]; float ctxs[VS];
                 float preds[VV]; float red[16], red2[16]; float cmb[4]; } at;
    } u;
};

// flash-style partial over [t0, t0+tl) of row n; writes d_pm/d_ps/d_pctx slot (n*2+ci)
__device__ void attn_part(SMem* sm, const float* __restrict__ key,
        const float* __restrict__ val, const float* __restrict__ h2row,
        int n, int ci, int t0, int tl) {
    const int tid = threadIdx.x, lane = tid & 31, wid = tid >> 5;
    float* ev = sm->u.at.ev;
    __syncthreads();
    if (tid < KSZ) sm->u.at.h2s[tid] = __ldcg(&h2row[tid]);
    __syncthreads();
    const float* krow = key + (size_t)t0*(NB*KSZ) + (size_t)n*KSZ + lane*4;
    const float* vrow = val + (size_t)t0*(NB*VS)  + (size_t)n*VS  + lane*4;
    float4 hv = *(const float4*)&sm->u.at.h2s[lane*4];
    float wmax = -3.0e38f;
    int t = wid;
    for (; t + 48 < tl; t += 64) {
        float4 k0 = *(const float4*)(krow + (size_t)(t     )*(NB*KSZ));
        float4 k1 = *(const float4*)(krow + (size_t)(t + 16)*(NB*KSZ));
        float4 k2 = *(const float4*)(krow + (size_t)(t + 32)*(NB*KSZ));
        float4 k3 = *(const float4*)(krow + (size_t)(t + 48)*(NB*KSZ));
        float s0 = k0.x*hv.x + k0.y*hv.y + k0.z*hv.z + k0.w*hv.w;
        float s1 = k1.x*hv.x + k1.y*hv.y + k1.z*hv.z + k1.w*hv.w;
        float s2 = k2.x*hv.x + k2.y*hv.y + k2.z*hv.z + k2.w*hv.w;
        float s3 = k3.x*hv.x + k3.y*hv.y + k3.z*hv.z + k3.w*hv.w;
        #pragma unroll
        for (int sh = 16; sh; sh >>= 1) {
            s0 += __shfl_xor_sync(~0u, s0, sh); s1 += __shfl_xor_sync(~0u, s1, sh);
            s2 += __shfl_xor_sync(~0u, s2, sh); s3 += __shfl_xor_sync(~0u, s3, sh);
        }
        if (lane == 0) { ev[t]=s0; ev[t+16]=s1; ev[t+32]=s2; ev[t+48]=s3; }
        wmax = fmaxf(wmax, fmaxf(fmaxf(s0,s1), fmaxf(s2,s3)));
    }
    for (; t < tl; t += 16) {
        float4 k0 = *(const float4*)(krow + (size_t)t*(NB*KSZ));
        float s0 = k0.x*hv.x + k0.y*hv.y + k0.z*hv.z + k0.w*hv.w;
        #pragma unroll
        for (int sh = 16; sh; sh >>= 1) s0 += __shfl_xor_sync(~0u, s0, sh);
        if (lane == 0) ev[t] = s0;
        wmax = fmaxf(wmax, s0);
    }
    if (lane == 0) sm->u.at.red[wid] = wmax;
    __syncthreads();
    float m = sm->u.at.red[0];
    #pragma unroll
    for (int w = 1; w < 16; w++) m = fmaxf(m, sm->u.at.red[w]);
    float psum = 0.f;
    if (tid < tl) { float w = expf(ev[tid] - m); ev[tid] = w; psum += w; }
    #pragma unroll
    for (int sh = 16; sh; sh >>= 1) psum += __shfl_xor_sync(~0u, psum, sh);
    if (lane == 0) sm->u.at.red2[wid] = psum;
    __syncthreads();
    float4 a0 = {0,0,0,0}, a1 = {0,0,0,0};
    t = wid;
    for (; t + 16 < tl; t += 32) {
        float e0 = ev[t], e1 = ev[t+16];
        float4 v0 = *(const float4*)(vrow + (size_t)(t     )*(NB*VS));
        float4 v1 = *(const float4*)(vrow + (size_t)(t + 16)*(NB*VS));
        a0.x += e0*v0.x; a0.y += e0*v0.y; a0.z += e0*v0.z; a0.w += e0*v0.w;
        a1.x += e1*v1.x; a1.y += e1*v1.y; a1.z += e1*v1.z; a1.w += e1*v1.w;
    }
    for (; t < tl; t += 16) {
        float e0 = ev[t];
        float4 v0 = *(const float4*)(vrow + (size_t)t*(NB*VS));
        a0.x += e0*v0.x; a0.y += e0*v0.y; a0.z += e0*v0.z; a0.w += e0*v0.w;
    }
    a0.x += a1.x; a0.y += a1.y; a0.z += a1.z; a0.w += a1.w;
    *(float4*)&sm->u.at.cpart[wid][lane*4] = a0;
    __syncthreads();
    if (tid < VS) {
        float s = 0.f;
        #pragma unroll
        for (int w = 0; w < 16; w++) s += sm->u.at.cpart[w][tid];
        d_pctx[((size_t)n*2 + ci)*VS + tid] = s;
    }
    if (tid == 0) {
        float st = 0.f;
        #pragma unroll
        for (int w = 0; w < 16; w++) st += sm->u.at.red2[w];
        d_pm[n*2 + ci] = m;
        d_ps[n*2 + ci] = st;
    }
}

__global__ void __launch_bounds__(512, 1) k_decode(
    const float* __restrict__ key, const float* __restrict__ val,
    const int* __restrict__ lens,
    const float* __restrict__ bih2, const float* __restrict__ bhh2,
    const float* __restrict__ Wout, const float* __restrict__ bout,
    float* __restrict__ out)
{
    extern __shared__ __align__(16) char smraw[];
    SMem* sm = (SMem*)smraw;
    const int bid = blockIdx.x, tid = threadIdx.x;
    const int lane = tid & 31, wid = tid >> 5;
    const int mt = bid & 31, n0 = (bid >> 5) * 32;
    const int rowA = d_srt[bid], rowB = d_srt[NBLK-1-bid];
    const int hA = d_half[rowA];
    const int hB = d_half[rowB], LB = lens[rowB];

    for (int step = 0; step < ML; step++) {
        const int p = step & 1;

        // ===== LSTM1: A staged once; W via plain LDG.128 (4 cols) + ALU pack =====
        {
            const float* h1in = d_h1[p];
            {
                int an = tid & 31, kb = tid >> 5;
                const float* src = h1in + (size_t)(n0 + an)*HH + kb*32;
                #pragma unroll
                for (int q = 0; q < 8; q++) {
                    float4 v = __ldcg((const float4*)(src + q*4));
                    int kk = kb*32 + q*4;
                    sm->u.l1.As[kk][an] = v.x; sm->u.l1.As[kk+1][an] = v.y;
                    sm->u.l1.As[kk+2][an] = v.z; sm->u.l1.As[kk+3][an] = v.w;
                }
            }
            __syncthreads();
            const int g = tid >> 7, t = tid & 127;
            const int np = t & 7, c4 = t >> 3;
            const float4* wp = (const float4*)(d_W1t + ((size_t)mt*512 + g*128)*64 + c4*4);
            ull acc[8] = {0,0,0,0,0,0,0,0};
            #pragma unroll 4
            for (int k = 0; k < 128; k++) {
                const float* ar = &sm->u.l1.As[g*128 + k][np*4];
                ull a0 = *(const ull*)ar, a1 = *(const ull*)(ar + 2);
                float4 w = wp[(size_t)k*16];
                ull b0 = pack2(w.x), b1 = pack2(w.y), b2 = pack2(w.z), b3 = pack2(w.w);
                ffma2(acc[0],a0,b0); ffma2(acc[1],a1,b0);
                ffma2(acc[2],a0,b1); ffma2(acc[3],a1,b1);
                ffma2(acc[4],a0,b2); ffma2(acc[5],a1,b2);
                ffma2(acc[6],a0,b3); ffma2(acc[7],a1,b3);
            }
            #pragma unroll
            for (int j = 0; j < 4; j++) {
                float2 v0 = unpack2(acc[2*j]), v1 = unpack2(acc[2*j+1]);
                float* gr = sm->u.l1.gt[g][c4*4 + j];
                gr[np*4] = v0.x; gr[np*4+1] = v0.y; gr[np*4+2] = v1.x; gr[np*4+3] = v1.y;
            }
            __syncthreads();
            int nl = tid >> 4, mi = tid & 15;
            int gn = n0 + nl, gm = mt*16 + mi;
            int tk = __ldcg(&d_tok[gn]);
            const float* tt = d_toktab + (size_t)tk*G1;
            const float* ic = d_inpc + (size_t)gn*G1;
            float g4[4];
            #pragma unroll
            for (int gg = 0; gg < 4; gg++) {
                int col = gg*16 + mi;
                g4[gg] = sm->u.l1.gt[0][col][nl] + sm->u.l1.gt[1][col][nl]
                       + sm->u.l1.gt[2][col][nl] + sm->u.l1.gt[3][col][nl]
                       + tt[gg*HH + gm] + ic[gg*HH + gm];
            }
            float cp = d_c1[gn*HH + gm];
            float cn = sigf(g4[1])*cp + sigf(g4[0])*tanhf(g4[2]);
            d_c1[gn*HH + gm] = cn;
            d_h1[p^1][gn*HH + gm] = sigf(g4[3])*tanhf(cn);
        }
        grid_bar();

        // ===== LSTM2 (unchanged from round 8) =====
        {
            const float* h1n = d_h1[p^1];
            const float* h2p = d_h2[p];
            {
                int an = tid & 31, kb = tid >> 5;
                #pragma unroll
                for (int q = 0; q < 10; q++) {
                    int kk = kb*40 + q*4;
                    float4 v = (kk < 512)
                        ? __ldcg((const float4*)(h1n + (size_t)(n0 + an)*HH  + kk))
                        : __ldcg((const float4*)(h2p + (size_t)(n0 + an)*KSZ + kk - 512));
                    sm->u.l2.As[kk][an] = v.x; sm->u.l2.As[kk+1][an] = v.y;
                    sm->u.l2.As[kk+2][an] = v.z; sm->u.l2.As[kk+3][an] = v.w;
                }
            }
            __syncthreads();
            const int g2 = tid >> 6, t2 = tid & 63;
            const int np = t2 & 7, c2 = t2 >> 3;
            const int kb2 = g2 * 80;
            const ulonglong2* bp = (const ulonglong2*)d_W2d + ((size_t)mt*640 + kb2)*8 + c2;
            ull A00=0, A01=0, A10=0, A11=0;
            #pragma unroll 8
            for (int k = 0; k < 80; k++) {
                const float* ar = &sm->u.l2.As[kb2 + k][np*4];
                ull a0 = *(const ull*)ar, a1 = *(const ull*)(ar + 2);
                ulonglong2 b = bp[(size_t)k*8];
                ffma2(A00, a0, b.x); ffma2(A10, a1, b.x);
                ffma2(A01, a0, b.y); ffma2(A11, a1, b.y);
            }
            { float2 v;
              v = unpack2(A00); sm->u.l2.gt[g2][2*c2  ][np*4  ] = v.x; sm->u.l2.gt[g2][2*c2  ][np*4+1] = v.y;
              v = unpack2(A10); sm->u.l2.gt[g2][2*c2  ][np*4+2] = v.x; sm->u.l2.gt[g2][2*c2  ][np*4+3] = v.y;
              v = unpack2(A01); sm->u.l2.gt[g2][2*c2+1][np*4  ] = v.x; sm->u.l2.gt[g2][2*c2+1][np*4+1] = v.y;
              v = unpack2(A11); sm->u.l2.gt[g2][2*c2+1][np*4+2] = v.x; sm->u.l2.gt[g2][2*c2+1][np*4+3] = v.y; }
            __syncthreads();
            {
                int cc = tid & 15, nl = tid >> 4;
                float s = 0.f;
                #pragma unroll
                for (int w = 0; w < 8; w++) s += sm->u.l2.gt[w][cc][nl];
                sm->u.l2.rs[cc][nl] = s;
            }
            __syncthreads();
            if (tid < 128) {
                int nl = tid >> 2, ci = tid & 3;
                int gn = n0 + nl, gm = mt*4 + ci;
                float g4[4];
                #pragma unroll
                for (int gg = 0; gg < 4; gg++) {
                    int r = gg*KSZ + gm;
                    g4[gg] = sm->u.l2.rs[gg*4 + ci][nl] + bih2[r] + bhh2[r];
                }
                float cp = d_c2[gn*KSZ + gm];
                float cn = sigf(g4[1])*cp + sigf(g4[0])*tanhf(g4[2]);
                d_c2[gn*KSZ + gm] = cn;
                d_h2[p^1][gn*KSZ + gm] = sigf(g4[3])*tanhf(cn);
            }
        }
        grid_bar();

        // ===== attention partials: 2 balanced units per block =====
        attn_part(sm, key, val, d_h2[p^1] + (size_t)rowA*KSZ, rowA, 0, 0, hA);
        attn_part(sm, key, val, d_h2[p^1] + (size_t)rowB*KSZ, rowB, 1, hB, LB - hB);
        grid_bar();

        // ===== combine + output proj + argmax (block = row) =====
        {
            const int n = bid;
            if (tid < KSZ) sm->u.at.h2s[tid] = __ldcg(&d_h2[p^1][(size_t)n*KSZ + tid]);
            if (tid == 0) {
                float m0 = __ldcg(&d_pm[2*n]),   m1 = __ldcg(&d_pm[2*n+1]);
                float s0 = __ldcg(&d_ps[2*n]),   s1 = __ldcg(&d_ps[2*n+1]);
                float M = fmaxf(m0, m1);
                float f0 = expf(m0 - M), f1 = expf(m1 - M);
                float S = f0*s0 + f1*s1;
                sm->u.at.cmb[0] = f0; sm->u.at.cmb[1] = f1; sm->u.at.cmb[2] = 1.0f / S;
            }
            __syncthreads();
            if (tid < VS) {
                float c0 = __ldcg(&d_pctx[(size_t)(2*n)*VS + tid]);
                float c1 = __ldcg(&d_pctx[(size_t)(2*n+1)*VS + tid]);
                sm->u.at.ctxs[tid] = (sm->u.at.cmb[0]*c0 + sm->u.at.cmb[1]*c1) * sm->u.at.cmb[2];
            }
            __syncthreads();
            for (int v = wid; v < VV; v += 16) {
                const float* wr = Wout + (size_t)v*(KSZ+VS);
                float s = 0.f;
                #pragma unroll
                for (int kk = 0; kk < 8; kk++) {
                    int k = lane + kk*32;
                    float x = (k < KSZ) ? sm->u.at.h2s[k] : sm->u.at.ctxs[k-KSZ];
                    s += x * wr[k];
                }
                #pragma unroll
                for (int sh = 16; sh; sh >>= 1) s += __shfl_xor_sync(~0u, s, sh);
                if (lane == 0) sm->u.at.preds[v] = s + bout[v];
            }
            __syncthreads();
            if (tid < VV) out[(size_t)n*ML*VV + (size_t)step*VV + tid] = sm->u.at.preds[tid];
            if (tid == 0) {
                float best = sm->u.at.preds[0]; int bi = 0;
                #pragma unroll
                for (int v = 1; v < VV; v++)
                    if (sm->u.at.preds[v] > best) { best = sm->u.at.preds[v]; bi = v; }
                d_tok[n] = bi;
            }
        }
        grid_bar();
    }
}

extern "C" void kernel_launch(void* const* d_in, const int* in_sizes, int n_in,
                              void* d_out, int out_size) {
    const float* key  = (const float*)d_in[0];
    const float* val  = (const float*)d_in[1];
    const int*   lens = (const int*)  d_in[2];
    const float* emb  = (const float*)d_in[3];
    const float* Wih1 = (const float*)d_in[4];
    const float* Whh1 = (const float*)d_in[5];
    const float* bih1 = (const float*)d_in[6];
    const float* bhh1 = (const float*)d_in[7];
    const float* Wih2 = (const float*)d_in[8];
    const float* Whh2 = (const float*)d_in[9];
    const float* bih2 = (const float*)d_in[10];
    const float* bhh2 = (const float*)d_in[11];
    const float* Wout = (const float*)d_in[12];
    const float* bout = (const float*)d_in[13];
    float* out = (float*)d_out;

    cudaFuncSetAttribute(k_decode, cudaFuncAttributeMaxDynamicSharedMemorySize,
                         (int)sizeof(SMem));
    k_pre<<<NB, 256>>>(val, emb, Wih1, bih1, bhh1, Whh1, Wih2, Whh2, lens);
    k_decode<<<NBLK, 512, sizeof(SMem)>>>(key, val, lens, bih2, bhh2, Wout, bout, out);
}